// round 3
// baseline (speedup 1.0000x reference)
#include <cuda_runtime.h>
#include <cstdint>

// LRAP loss, B x C = 16384 x 2048.
// Per-row bucket-counting rank computation (no sort), exact tie handling
// matching JAX stable argsort (smaller index wins on equal preds).

#define NCLS   2048
#define THREADS 256
#define EPT     8     // elements per thread = NCLS/THREADS

__device__ double g_rowscore[16384];

__device__ __forceinline__ uint32_t orderFloat(float f) {
    uint32_t u = __float_as_uint(f);
    return (u & 0x80000000u) ? ~u : (u | 0x80000000u);  // monotone increasing
}

__global__ __launch_bounds__(THREADS)
void lrap_row_kernel(const float* __restrict__ preds,
                     const float* __restrict__ labels) {
    const int row = blockIdx.x;
    const int t   = threadIdx.x;
    const float4* p4 = (const float4*)(preds  + (size_t)row * NCLS);
    const float4* l4 = (const float4*)(labels + (size_t)row * NCLS);

    __shared__ uint32_t           hist[NCLS];    // lo16 = count, hi16 = pos count
    __shared__ uint32_t           base_[NCLS];   // exclusive prefix (packed)
    __shared__ uint32_t           cursor[NCLS];  // scatter cursors (lo part)
    __shared__ unsigned long long scat[NCLS];    // bucket-grouped entries
    __shared__ uint32_t warpSums[8];
    __shared__ double   redS[8];
    __shared__ int      redN[8];

    // -- zero histogram --
    #pragma unroll
    for (int i = 0; i < NCLS / THREADS; i++) hist[t + i * THREADS] = 0u;
    __syncthreads();

    // -- phase A: load row, bin, histogram --
    unsigned long long ent[EPT];
    int      bkt[EPT];
    uint32_t labm = 0;

    #pragma unroll
    for (int i = 0; i < 2; i++) {
        int q = t + i * THREADS;            // float4 index within the row
        float4 pv = p4[q];
        float4 lv = l4[q];
        float px[4] = {pv.x, pv.y, pv.z, pv.w};
        float lx[4] = {lv.x, lv.y, lv.z, lv.w};
        #pragma unroll
        for (int c = 0; c < 4; c++) {
            int e = i * 4 + c;
            int j = q * 4 + c;              // column index 0..2047
            uint32_t ou = orderFloat(px[c]);
            int bin = __float2int_rd((px[c] + 4.0f) * 256.0f);
            bin = max(0, min(2047, bin));
            int b = 2047 - bin;             // smaller b  <=>  larger pred  <=> smaller rank
            uint32_t lab = (lx[c] > 0.5f) ? 1u : 0u;
            labm |= lab << e;
            bkt[e] = b;
            // key = (ou << 11) | (2047 - j): bigger key <=> better (smaller) rank,
            // ties broken by smaller original index, exactly like stable argsort.
            ent[e] = ((unsigned long long)ou << 12)
                   | ((unsigned long long)(2047 - j) << 1)
                   | (unsigned long long)lab;
            atomicAdd(&hist[b], 1u + (lab << 16));
        }
    }
    __syncthreads();

    // -- phase B: exclusive prefix sum over 2048 packed counters --
    uint32_t loc[8];
    uint32_t s = 0;
    #pragma unroll
    for (int i = 0; i < 8; i++) { loc[i] = s; s += hist[t * 8 + i]; }
    uint32_t inc = s;
    const int lane = t & 31, wid = t >> 5;
    #pragma unroll
    for (int off = 1; off < 32; off <<= 1) {
        uint32_t n = __shfl_up_sync(0xffffffffu, inc, off);
        if (lane >= off) inc += n;
    }
    if (lane == 31) warpSums[wid] = inc;
    __syncthreads();
    if (t == 0) {
        uint32_t acc = 0;
        #pragma unroll
        for (int w = 0; w < 8; w++) { uint32_t v = warpSums[w]; warpSums[w] = acc; acc += v; }
    }
    __syncthreads();
    const uint32_t exclT = warpSums[wid] + (inc - s);
    #pragma unroll
    for (int i = 0; i < 8; i++) {
        uint32_t bv = exclT + loc[i];
        base_[t * 8 + i]  = bv;
        cursor[t * 8 + i] = bv & 0xFFFFu;
    }
    __syncthreads();

    // -- phase C: scatter entries into bucket order --
    #pragma unroll
    for (int e = 0; e < EPT; e++) {
        uint32_t slot = atomicAdd(&cursor[bkt[e]], 1u);
        scat[slot] = ent[e];
    }
    __syncthreads();

    // -- phase D: for each positive, exact rank via tiny in-bucket scan --
    float sc = 0.0f;
    int npos = __popc(labm);
    #pragma unroll
    for (int e = 0; e < EPT; e++) {
        if ((labm >> e) & 1u) {
            int b = bkt[e];
            uint32_t bb    = base_[b];
            uint32_t start = bb & 0xFFFFu;     // # elements strictly better-bucketed
            uint32_t pB    = bb >> 16;         // # positives strictly better-bucketed
            uint32_t cnt   = hist[b] & 0xFFFFu;
            unsigned long long key = ent[e] >> 1;
            uint32_t gt = 0, pg = 0;
            for (uint32_t m = start; m < start + cnt; m++) {
                unsigned long long ee = scat[m];
                if ((ee >> 1) > key) { gt++; pg += (uint32_t)(ee & 1ull); }
            }
            float rank = (float)(start + gt + 1);
            float ple  = (float)(pB + pg + 1);
            sc += __fdividef(ple, rank);
        }
    }

    // -- phase E: block reduce, write per-row score --
    double d = (double)sc;
    #pragma unroll
    for (int off = 16; off; off >>= 1) {
        d    += __shfl_down_sync(0xffffffffu, d, off);
        npos += __shfl_down_sync(0xffffffffu, npos, off);
    }
    if (lane == 0) { redS[wid] = d; redN[wid] = npos; }
    __syncthreads();
    if (t == 0) {
        double tot = 0.0; int np = 0;
        #pragma unroll
        for (int w = 0; w < 8; w++) { tot += redS[w]; np += redN[w]; }
        g_rowscore[row] = tot / (double)np;
    }
}

__global__ void lrap_reduce_kernel(float* __restrict__ out, int B) {
    __shared__ double red[32];
    double s = 0.0;
    for (int i = threadIdx.x; i < B; i += blockDim.x) s += g_rowscore[i];
    const int lane = threadIdx.x & 31, wid = threadIdx.x >> 5;
    #pragma unroll
    for (int off = 16; off; off >>= 1) s += __shfl_down_sync(0xffffffffu, s, off);
    if (lane == 0) red[wid] = s;
    __syncthreads();
    if (threadIdx.x == 0) {
        double tot = 0.0;
        int nw = blockDim.x >> 5;
        for (int w = 0; w < nw; w++) tot += red[w];
        out[0] = (float)(tot / (double)B);
    }
}

extern "C" void kernel_launch(void* const* d_in, const int* in_sizes, int n_in,
                              void* d_out, int out_size) {
    const float* preds  = (const float*)d_in[0];
    const float* labels = (const float*)d_in[1];
    float* out = (float*)d_out;

    int B = in_sizes[0] / NCLS;
    if (B > 16384) B = 16384;   // scratch capacity

    lrap_row_kernel<<<B, THREADS>>>(preds, labels);
    lrap_reduce_kernel<<<1, 1024>>>(out, B);
}